// round 11
// baseline (speedup 1.0000x reference)
#include <cuda_runtime.h>
#include <cstdint>
#include <cstddef>

#define NBATCH 256
#define NT     2048
#define NFIN   32
#define NHID   64
#define NPOS   (NBATCH * NT)   // 524288

typedef unsigned long long u64;

// ---------------- scratch (static device globals: allocation-free) ----------
__device__ u64   g_env1t[(size_t)32 * NPOS];            // L1 output, pair-major [pair][idx]
__device__ float g_gin0[(size_t)NPOS * 256];            // L0 gate input-proj
__device__ float g_f1[(size_t)NPOS * NHID];             // fusion feat1 (transposed pairs)
__device__ float4 g_wh0s[8 * 16 * 32];                  // staged Whh0 (64 KB)
__device__ float g_traj[366 * 8];                       // ODE trajectory

// ---------------- fast activations (fp32, ~1e-6 rel err) -------------------
__device__ __forceinline__ float fsig(float x) {
    return __fdividef(1.0f, 1.0f + __expf(-x));
}
__device__ __forceinline__ float ftanh(float x) {
    float ax = fabsf(x);
    float e  = __expf(-2.0f * ax);
    float r  = __fdividef(1.0f - e, 1.0f + e);
    return copysignf(r, x);
}

// ---------------- packed f32x2 helpers --------------------------------------
__device__ __forceinline__ u64 pack2(float lo, float hi) {
    u64 r; asm("mov.b64 %0, {%1, %2};" : "=l"(r) : "f"(lo), "f"(hi)); return r;
}
__device__ __forceinline__ void fma2(u64& a, u64 w, u64 v) {
    asm("fma.rn.f32x2 %0, %1, %2, %0;" : "+l"(a) : "l"(w), "l"(v));
}
__device__ __forceinline__ float hsum2(u64 a) {
    float lo, hi; asm("mov.b64 {%0, %1}, %2;" : "=f"(lo), "=f"(hi) : "l"(a));
    return lo + hi;
}
__device__ __forceinline__ void unpack2(u64 a, float& lo, float& hi) {
    asm("mov.b64 {%0, %1}, %2;" : "=f"(lo), "=f"(hi) : "l"(a));
}

// ---------------- ODE body (runs as blockIdx == 128 of fused rec) ----------
// Safe for blockDim 512: extra threads only hit benign duplicate writes.
__device__ void ode_body(int tid,
                         const float* __restrict__ h0,
                         const float* __restrict__ W1, const float* __restrict__ b1,
                         const float* __restrict__ W2, const float* __restrict__ b2,
                         const float* __restrict__ W3, const float* __restrict__ b3)
{
    __shared__ float sInp[12];
    __shared__ float sz1[64];
    __shared__ float sz2[64];
    __shared__ float sk[6][8];
    __shared__ float shh[8];
    __shared__ __align__(16) float sW3[8 * 64];
    __shared__ float sb3[8];

    float w1r[9];
    float w2r[64];
    float b1j = 0.f, b2j = 0.f;
    if (tid < 64) {
#pragma unroll
        for (int k = 0; k < 9; ++k) w1r[k] = W1[tid * 9 + k];
#pragma unroll
        for (int k = 0; k < 64; ++k) w2r[k] = W2[tid * 64 + k];
        b1j = b1[tid];
        b2j = b2[tid];
    }
    for (int i = tid; i < 8 * 64; i += 512) sW3[i] = W3[i];
    if (tid < 8) {
        sb3[tid] = b3[tid];
        shh[tid] = h0[tid];
        g_traj[tid] = h0[tid];
    }
    __syncthreads();

    const float dt = 1.0f / 365.0f;

    for (int d = 0; d < 365; ++d) {
        float t0 = (float)d * dt;
#pragma unroll 1
        for (int s = 0; s < 6; ++s) {
            if (tid < 8) {
                float v = shh[tid];
                if (s == 1) v += dt * (0.2f * sk[0][tid]);
                else if (s == 2) v += dt * ((3.f/40.f)*sk[0][tid] + (9.f/40.f)*sk[1][tid]);
                else if (s == 3) v += dt * ((44.f/45.f)*sk[0][tid] - (56.f/15.f)*sk[1][tid] + (32.f/9.f)*sk[2][tid]);
                else if (s == 4) v += dt * ((19372.f/6561.f)*sk[0][tid] - (25360.f/2187.f)*sk[1][tid]
                                          + (64448.f/6561.f)*sk[2][tid] - (212.f/729.f)*sk[3][tid]);
                else if (s == 5) v += dt * ((9017.f/3168.f)*sk[0][tid] - (355.f/33.f)*sk[1][tid]
                                          + (46732.f/5247.f)*sk[2][tid] + (49.f/176.f)*sk[3][tid]
                                          - (5103.f/18656.f)*sk[4][tid]);
                sInp[tid] = v;
            }
            if (tid == 8) {
                float cn;
                if (s == 0) cn = 0.0f;
                else if (s == 1) cn = 0.2f;
                else if (s == 2) cn = 0.3f;
                else if (s == 3) cn = 0.8f;
                else if (s == 4) cn = 8.f/9.f;
                else cn = 1.0f;
                sInp[8] = t0 + cn * dt;
            }
            __syncthreads();
            if (tid < 64) {
                float a = b1j;
#pragma unroll
                for (int k = 0; k < 9; ++k) a = fmaf(w1r[k], sInp[k], a);
                sz1[tid] = ftanh(a);
            }
            __syncthreads();
            if (tid < 64) {
                float a0 = b2j, a1 = 0.f, a2 = 0.f, a3 = 0.f;
#pragma unroll
                for (int k = 0; k < 64; k += 4) {
                    a0 = fmaf(w2r[k+0], sz1[k+0], a0);
                    a1 = fmaf(w2r[k+1], sz1[k+1], a1);
                    a2 = fmaf(w2r[k+2], sz1[k+2], a2);
                    a3 = fmaf(w2r[k+3], sz1[k+3], a3);
                }
                sz2[tid] = ftanh((a0 + a1) + (a2 + a3));
            }
            __syncthreads();
            if (tid < 8) {
                float a0 = sb3[tid], a1 = 0.f, a2 = 0.f, a3 = 0.f;
#pragma unroll
                for (int k = 0; k < 64; k += 4) {
                    a0 = fmaf(sW3[tid*64 + k+0], sz2[k+0], a0);
                    a1 = fmaf(sW3[tid*64 + k+1], sz2[k+1], a1);
                    a2 = fmaf(sW3[tid*64 + k+2], sz2[k+2], a2);
                    a3 = fmaf(sW3[tid*64 + k+3], sz2[k+3], a3);
                }
                sk[s][tid] = (a0 + a1) + (a2 + a3);
            }
            __syncthreads();
        }
        if (tid < 8) {
            float hn = shh[tid] + dt * ((35.f/384.f)   * sk[0][tid]
                                      + (500.f/1113.f) * sk[2][tid]
                                      + (125.f/192.f)  * sk[3][tid]
                                      - (2187.f/6784.f)* sk[4][tid]
                                      + (11.f/84.f)    * sk[5][tid]);
            shh[tid] = hn;
            g_traj[(d + 1) * 8 + tid] = hn;
        }
        __syncthreads();
    }
}

// ============================================================================
// Stage Whh0 into lane-coalesced layout.
// ============================================================================
__global__ void k_stage(const float* __restrict__ Whh0)
{
    int e = blockIdx.x * 256 + threadIdx.x;   // grid 16 x 256 = 4096
    int l  = e & 31;
    int kp = (e >> 5) & 15;
    int w  = e >> 9;
    int r  = (l >> 3) * 64 + (w << 3) + (l & 7);
    g_wh0s[e] = *(const float4*)(Whh0 + r * 64 + kp * 4);
}

// ============================================================================
// L0 gate input-projection GEMM (f32x2), 4 CTAs/SM.
// ============================================================================
__global__ __launch_bounds__(256, 4) void k_gates0(
    const float* __restrict__ X,
    const float* __restrict__ Wih,
    const float* __restrict__ bih, const float* __restrict__ bhh,
    float* __restrict__ gout)
{
    __shared__ __align__(16) float xs[128 * NFIN];      // 16 kB
    const int tid = threadIdx.x;
    const size_t pos0 = (size_t)blockIdx.x * 128;

    const float4* xg = (const float4*)(X + pos0 * NFIN);
    float4* xs4 = (float4*)xs;
#pragma unroll
    for (int i = 0; i < 4; ++i) xs4[tid + 256 * i] = xg[tid + 256 * i];

    u64 wrp[16];
    {
        const u64* wp = (const u64*)(Wih + tid * NFIN);
#pragma unroll
        for (int k = 0; k < 16; ++k) wrp[k] = wp[k];
    }
    const float bias = bih[tid] + bhh[tid];
    __syncthreads();

#pragma unroll 1
    for (int p = 0; p < 128; p += 2) {
        u64 a0 = pack2(bias, 0.f), a1 = pack2(bias, 0.f);
        const ulonglong2* x0 = (const ulonglong2*)(xs + (p+0) * NFIN);
        const ulonglong2* x1 = (const ulonglong2*)(xs + (p+1) * NFIN);
#pragma unroll
        for (int k2 = 0; k2 < 8; ++k2) {
            ulonglong2 v0 = x0[k2], v1 = x1[k2];
            fma2(a0, wrp[2*k2], v0.x); fma2(a0, wrp[2*k2+1], v0.y);
            fma2(a1, wrp[2*k2], v1.x); fma2(a1, wrp[2*k2+1], v1.y);
        }
        gout[(pos0 + p + 0) * 256 + tid] = hsum2(a0);
        gout[(pos0 + p + 1) * 256 + tid] = hsum2(a1);
    }
}

// ============================================================================
// Fused recurrence, k-split: 512 threads/CTA, 2 rows, 128 CTAs (+ODE at 128).
// Thread (tid) -> kh = tid>>8 (k-half), t = tid&255 -> (gate gt, unit u) as
// before. Each thread holds HALF of each weight row: 48 u64 = 96 regs ->
// register-resident at the 128-reg/thread budget. Halves exchange 4 partial
// sums via smem; k-lo threads run the activation/cell tail. 2 barriers/step.
// env1 written transposed-pair-major for coalesced fusA reads.
// ============================================================================
__global__ __launch_bounds__(512, 1) void k_recfused(
    const float* __restrict__ Wih1g, const float* __restrict__ Whh1g,
    const float* __restrict__ bih1g, const float* __restrict__ bhh1g,
    const float* __restrict__ h0ode,
    const float* __restrict__ oW1, const float* __restrict__ ob1,
    const float* __restrict__ oW2, const float* __restrict__ ob2,
    const float* __restrict__ oW3, const float* __restrict__ ob3)
{
    const int tid = threadIdx.x;
    if (blockIdx.x == 128) {
        ode_body(tid, h0ode, oW1, ob1, oW2, ob2, oW3, ob3);
        return;
    }
    const int kh = tid >> 8;          // 0 = k in [0,32), 1 = k in [32,64)
    const int t  = tid & 255;
    const int w  = t >> 5, l = t & 31;
    const int gt = l >> 3;
    const int u  = (w << 3) | (l & 7);
    const int r  = gt * 64 + u;
    const int lb = l & 7;
    const int koff = kh << 5;
    const unsigned FULL = 0xffffffffu;

    // half-row weights (register-resident: 48 u64)
    u64 ws[16], wi1[16], wh1[16];
    {
        const u64* p1 = (const u64*)(Wih1g + r * 64 + koff);
        const u64* p2 = (const u64*)(Whh1g + r * 64 + koff);
#pragma unroll
        for (int k = 0; k < 16; ++k) { wi1[k] = p1[k]; wh1[k] = p2[k]; }
        const char* wsb = (const char*)(g_wh0s + (size_t)(w * 16 + kh * 8) * 32 + l);
#pragma unroll
        for (int kp = 0; kp < 8; ++kp) {
            ulonglong2 u2 = *(const ulonglong2*)(wsb + (size_t)kp * 512);
            ws[2*kp] = u2.x; ws[2*kp+1] = u2.y;
        }
    }
    const float bias1 = bih1g[r] + bhh1g[r];

    __shared__ __align__(16) float hs0[2][2][NHID];
    __shared__ __align__(16) float hs1[2][2][NHID];
    __shared__ float sPart[4][256];
    if (tid < 256) { ((float*)hs0)[tid] = 0.0f; ((float*)hs1)[tid] = 0.0f; }

    const int b0 = blockIdx.x * 2;
    const float* gA = g_gin0 + (size_t)b0 * NT * 256;
    const float* gB = gA + (size_t)NT * 256;
    const int idxA0 = b0 * NT;            // env1t index base, row A
    const int idxB0 = idxA0 + NT;         // row B
    const bool isg = (gt == 2);

    float c0A = 0.f, c0B = 0.f, c1A = 0.f, c1B = 0.f;
    float gnA = 0.f, gnB = 0.f, gxA = 0.f, gxB = 0.f;
    if (kh == 0) {
        gnA = gA[r];        gnB = gB[r];          // gin step 0
        gxA = gA[256 + r];  gxB = gB[256 + r];    // gin step 1
    }
    __syncthreads();

    // ---- s = 0: L0 only; h0[-1] = 0 so gate = gin0[0]. k-lo tail only. ----
    if (kh == 0) {
        float actA = isg ? ftanh(gnA) : fsig(gnA);
        float actB = isg ? ftanh(gnB) : fsig(gnB);
        float iA = __shfl_sync(FULL, actA, lb);
        float gA_ = __shfl_sync(FULL, actA, lb + 16);
        float oA = __shfl_sync(FULL, actA, lb + 24);
        float iB = __shfl_sync(FULL, actB, lb);
        float gB_ = __shfl_sync(FULL, actB, lb + 16);
        float oB = __shfl_sync(FULL, actB, lb + 24);
        c0A = iA * gA_;
        c0B = iB * gB_;
        float hA = oA * ftanh(c0A);
        float hB = oB * ftanh(c0B);
        if (gt == 0) { hs0[1][0][u] = hA; hs0[1][1][u] = hB; }
        gnA = gxA; gnB = gxB;
        gxA = gA[512 + r]; gxB = gB[512 + r];      // gin step 2
    }
    __syncthreads();

    // ---- main loop s = 1 .. NT-1 ----
#pragma unroll 1
    for (int s = 1; s < NT; ++s) {
        const int cur = s & 1;
        const float* h0A = hs0[cur][0] + koff;
        const float* h0B = hs0[cur][1] + koff;
        const float* h1A = hs1[cur][0] + koff;
        const float* h1B = hs1[cur][1] + koff;

        u64 aA = (kh == 0) ? pack2(gnA, 0.f) : 0;
        u64 aB = (kh == 0) ? pack2(gnB, 0.f) : 0;
        u64 qA = (kh == 0) ? pack2(bias1, 0.f) : 0;
        u64 qB = 0;
#pragma unroll
        for (int k = 0; k < 32; k += 4) {
            ulonglong2 vA = *(const ulonglong2*)(h0A + k);
            ulonglong2 vB = *(const ulonglong2*)(h0B + k);
            ulonglong2 uA = *(const ulonglong2*)(h1A + k);
            ulonglong2 uB = *(const ulonglong2*)(h1B + k);
            const int kk = k >> 1;
            fma2(aA, ws[kk], vA.x);   fma2(aA, ws[kk+1], vA.y);
            fma2(aB, ws[kk], vB.x);   fma2(aB, ws[kk+1], vB.y);
            fma2(qA, wi1[kk], vA.x);  fma2(qA, wi1[kk+1], vA.y);
            fma2(qA, wh1[kk], uA.x);  fma2(qA, wh1[kk+1], uA.y);
            fma2(qB, wi1[kk], vB.x);  fma2(qB, wi1[kk+1], vB.y);
            fma2(qB, wh1[kk], uB.x);  fma2(qB, wh1[kk+1], uB.y);
        }

        float m0A = hsum2(aA);
        float m0B = hsum2(aB);
        float m1A = hsum2(qA);
        float m1B = hsum2(qB);

        if (kh) {
            sPart[0][t] = m0A; sPart[1][t] = m0B;
            sPart[2][t] = m1A; sPart[3][t] = m1B;
        } else {
            // rotate gin prefetch (cover DRAM latency 2 steps ahead)
            gnA = gxA; gnB = gxB;
            if (s + 2 < NT) {
                gxA = gA[(size_t)(s + 2) * 256 + r];
                gxB = gB[(size_t)(s + 2) * 256 + r];
            }
        }
        __syncthreads();                 // barrier 1: partials visible

        if (kh == 0) {
            float p0A = m0A + sPart[0][t];
            float p0B = m0B + sPart[1][t];
            float p1A = m1A + sPart[2][t];
            float p1B = m1B + sPart[3][t];
            float act0A = isg ? ftanh(p0A) : fsig(p0A);
            float act0B = isg ? ftanh(p0B) : fsig(p0B);
            float act1A = isg ? ftanh(p1A) : fsig(p1A);
            float act1B = isg ? ftanh(p1B) : fsig(p1B);

            float i0A = __shfl_sync(FULL, act0A, lb);
            float f0A = __shfl_sync(FULL, act0A, lb + 8);
            float g0A = __shfl_sync(FULL, act0A, lb + 16);
            float o0A = __shfl_sync(FULL, act0A, lb + 24);
            float i0B = __shfl_sync(FULL, act0B, lb);
            float f0B = __shfl_sync(FULL, act0B, lb + 8);
            float g0B = __shfl_sync(FULL, act0B, lb + 16);
            float o0B = __shfl_sync(FULL, act0B, lb + 24);
            float i1A = __shfl_sync(FULL, act1A, lb);
            float f1A = __shfl_sync(FULL, act1A, lb + 8);
            float g1A = __shfl_sync(FULL, act1A, lb + 16);
            float o1A = __shfl_sync(FULL, act1A, lb + 24);
            float i1B = __shfl_sync(FULL, act1B, lb);
            float f1B = __shfl_sync(FULL, act1B, lb + 8);
            float g1B = __shfl_sync(FULL, act1B, lb + 16);
            float o1B = __shfl_sync(FULL, act1B, lb + 24);

            c0A = f0A * c0A + i0A * g0A;
            c0B = f0B * c0B + i0B * g0B;
            c1A = f1A * c1A + i1A * g1A;
            c1B = f1B * c1B + i1B * g1B;
            float h0nA = o0A * ftanh(c0A);
            float h0nB = o0B * ftanh(c0B);
            float h1nA = o1A * ftanh(c1A);
            float h1nB = o1B * ftanh(c1B);

            // neighbor h1 for packed transposed env1 store
            float h1hA = __shfl_down_sync(FULL, h1nA, 1);
            float h1hB = __shfl_down_sync(FULL, h1nB, 1);

            if (gt == 0) {
                hs0[cur ^ 1][0][u] = h0nA;
                hs0[cur ^ 1][1][u] = h0nB;
                hs1[cur ^ 1][0][u] = h1nA;
                hs1[cur ^ 1][1][u] = h1nB;
                if (!(lb & 1)) {
                    size_t p = (size_t)(u >> 1) * NPOS;
                    g_env1t[p + idxA0 + (s - 1)] = pack2(h1nA, h1hA);
                    g_env1t[p + idxB0 + (s - 1)] = pack2(h1nB, h1hB);
                }
            }
        }
        __syncthreads();                 // barrier 2: hs ready for next step
    }

    // ---- s = NT: L1 only, computing step NT-1 ----
    {
        const int cur = NT & 1;   // 0
        const float* h0A = hs0[cur][0] + koff;
        const float* h0B = hs0[cur][1] + koff;
        const float* h1A = hs1[cur][0] + koff;
        const float* h1B = hs1[cur][1] + koff;
        u64 qA = (kh == 0) ? pack2(bias1, 0.f) : 0;
        u64 qB = 0;
#pragma unroll
        for (int k = 0; k < 32; k += 4) {
            ulonglong2 vA = *(const ulonglong2*)(h0A + k);
            ulonglong2 vB = *(const ulonglong2*)(h0B + k);
            ulonglong2 uA = *(const ulonglong2*)(h1A + k);
            ulonglong2 uB = *(const ulonglong2*)(h1B + k);
            const int kk = k >> 1;
            fma2(qA, wi1[kk], vA.x);  fma2(qA, wi1[kk+1], vA.y);
            fma2(qA, wh1[kk], uA.x);  fma2(qA, wh1[kk+1], uA.y);
            fma2(qB, wi1[kk], vB.x);  fma2(qB, wi1[kk+1], vB.y);
            fma2(qB, wh1[kk], uB.x);  fma2(qB, wh1[kk+1], uB.y);
        }
        float m1A = hsum2(qA);
        float m1B = hsum2(qB);
        if (kh) { sPart[2][t] = m1A; sPart[3][t] = m1B; }
        __syncthreads();
        if (kh == 0) {
            float p1A = m1A + sPart[2][t];
            float p1B = m1B + sPart[3][t];
            float act1A = isg ? ftanh(p1A) : fsig(p1A);
            float act1B = isg ? ftanh(p1B) : fsig(p1B);

            float i1A = __shfl_sync(FULL, act1A, lb);
            float f1A = __shfl_sync(FULL, act1A, lb + 8);
            float g1A = __shfl_sync(FULL, act1A, lb + 16);
            float o1A = __shfl_sync(FULL, act1A, lb + 24);
            float i1B = __shfl_sync(FULL, act1B, lb);
            float f1B = __shfl_sync(FULL, act1B, lb + 8);
            float g1B = __shfl_sync(FULL, act1B, lb + 16);
            float o1B = __shfl_sync(FULL, act1B, lb + 24);

            c1A = f1A * c1A + i1A * g1A;
            c1B = f1B * c1B + i1B * g1B;
            float h1nA = o1A * ftanh(c1A);
            float h1nB = o1B * ftanh(c1B);
            float h1hA = __shfl_down_sync(FULL, h1nA, 1);
            float h1hB = __shfl_down_sync(FULL, h1nB, 1);
            if (gt == 0 && !(lb & 1)) {
                size_t p = (size_t)(u >> 1) * NPOS;
                g_env1t[p + idxA0 + (NT - 1)] = pack2(h1nA, h1hA);
                g_env1t[p + idxB0 + (NT - 1)] = pack2(h1nB, h1hB);
            }
        }
    }
}

// ============================================================================
// Fusion stage A: feat1 = relu(fus_W1 @ z + fb1). 2 CTAs/SM.
// z loads now fully coalesced from transposed env1; 4 accumulator chains.
// ============================================================================
__global__ __launch_bounds__(256, 2) void k_fusA(
    const int*   __restrict__ day_ids,
    const float* __restrict__ raw,
    const float* __restrict__ fW1, const float* __restrict__ fb1)
{
    const int tid = threadIdx.x;
    __shared__ __align__(16) float sW1[64 * 76];   // fus_W1 padded 73 -> 76
    __shared__ float sb1[64];

    for (int i = tid; i < 64 * 76; i += 256) {
        int j = i / 76, k = i - j * 76;
        sW1[i] = (k < 73) ? fW1[j * 73 + k] : 0.0f;
    }
    if (tid < 64) sb1[tid] = fb1[tid];
    __syncthreads();

    const int idx = blockIdx.x * 256 + tid;
    const int b = idx >> 11;

    u64 zp[38];
#pragma unroll
    for (int j = 0; j < 32; ++j)
        zp[j] = g_env1t[(size_t)j * NPOS + idx];   // coalesced
    const int day = day_ids[b];
#pragma unroll
    for (int i = 0; i < 4; ++i)
        zp[32 + i] = pack2(g_traj[day * 8 + 2*i], g_traj[day * 8 + 2*i + 1]);

    float4 rv = ((const float4*)raw)[idx];
    float iphys = rv.x * 9.0f * (1.0f + 0.0005f * (rv.y - 0.5f));
    zp[36] = pack2(iphys, 0.f);
    zp[37] = 0;

    u64* f1out = (u64*)g_f1;
#pragma unroll 1
    for (int j = 0; j < 64; j += 2) {
        u64 a0x = pack2(sb1[j], 0.f),   a0y = 0;
        u64 a1x = pack2(sb1[j+1], 0.f), a1y = 0;
        const ulonglong2* w0 = (const ulonglong2*)(sW1 + (j+0) * 76);
        const ulonglong2* w1 = (const ulonglong2*)(sW1 + (j+1) * 76);
#pragma unroll
        for (int k2 = 0; k2 < 19; ++k2) {
            ulonglong2 x0 = w0[k2], x1 = w1[k2];
            if (k2 < 10) {
                fma2(a0x, x0.x, zp[2*k2]); fma2(a0x, x0.y, zp[2*k2+1]);
                fma2(a1x, x1.x, zp[2*k2]); fma2(a1x, x1.y, zp[2*k2+1]);
            } else {
                fma2(a0y, x0.x, zp[2*k2]); fma2(a0y, x0.y, zp[2*k2+1]);
                fma2(a1y, x1.x, zp[2*k2]); fma2(a1y, x1.y, zp[2*k2+1]);
            }
        }
        f1out[(size_t)(j >> 1) * NPOS + idx] =
            pack2(fmaxf(hsum2(a0x) + hsum2(a0y), 0.f),
                  fmaxf(hsum2(a1x) + hsum2(a1y), 0.f));
    }
}

// ============================================================================
// Fusion stage B: f1 -> f2 -> r1 -> outputs. 2 CTAs/SM; 4 chains in f2 dots.
// ============================================================================
__global__ __launch_bounds__(256, 2) void k_fusB(
    const int*   __restrict__ day_ids,
    const float* __restrict__ raw,
    const float* __restrict__ hdw, const float* __restrict__ hdb,
    const float* __restrict__ fW2, const float* __restrict__ fb2,
    const float* __restrict__ rW1, const float* __restrict__ rb1,
    const float* __restrict__ rW2, const float* __restrict__ rb2,
    float* __restrict__ out)
{
    const int tid = threadIdx.x;

    __shared__ __align__(16) float sW2[64 * 64];    // 16 kB (row-major)
    __shared__ __align__(16) u64   sR1t[64 * 16];   // 8 kB: [k][J]
    __shared__ __align__(16) float sR2[32];
    __shared__ float sb2[64], srb1[32];
    __shared__ float shdw[8];
    __shared__ float sscal[2];

    for (int i = tid; i < 64 * 64; i += 256) sW2[i] = fW2[i];
    for (int i = tid; i < 64 * 16; i += 256) {
        int k = i >> 4, J = i & 15;
        sR1t[i] = pack2(rW1[(2*J) * 64 + k], rW1[(2*J+1) * 64 + k]);
    }
    if (tid < 64) sb2[tid] = fb2[tid];
    if (tid < 32) { sR2[tid] = rW2[tid]; srb1[tid] = rb1[tid]; }
    if (tid < 8)  shdw[tid] = hdw[tid];
    if (tid == 0) { sscal[0] = hdb[0]; sscal[1] = rb2[0]; }
    __syncthreads();

    const int idx = blockIdx.x * 256 + tid;
    const int b = idx >> 11;

    u64 f1p[32];
    const u64* f1in = (const u64*)g_f1;
#pragma unroll
    for (int k2 = 0; k2 < 32; ++k2)
        f1p[k2] = f1in[(size_t)k2 * NPOS + idx];

    u64 r1acc[16];
#pragma unroll
    for (int J = 0; J < 16; ++J) r1acc[J] = pack2(srb1[2*J], srb1[2*J+1]);

#pragma unroll 1
    for (int jp = 0; jp < 32; ++jp) {
        u64 a0x = pack2(sb2[2*jp], 0.f),   a0y = 0;
        u64 a1x = pack2(sb2[2*jp+1], 0.f), a1y = 0;
        const ulonglong2* w0 = (const ulonglong2*)(sW2 + (2*jp+0) * 64);
        const ulonglong2* w1 = (const ulonglong2*)(sW2 + (2*jp+1) * 64);
#pragma unroll
        for (int k2 = 0; k2 < 16; ++k2) {
            ulonglong2 x0 = w0[k2], x1 = w1[k2];
            if (k2 < 8) {
                fma2(a0x, x0.x, f1p[2*k2]); fma2(a0x, x0.y, f1p[2*k2+1]);
                fma2(a1x, x1.x, f1p[2*k2]); fma2(a1x, x1.y, f1p[2*k2+1]);
            } else {
                fma2(a0y, x0.x, f1p[2*k2]); fma2(a0y, x0.y, f1p[2*k2+1]);
                fma2(a1y, x1.x, f1p[2*k2]); fma2(a1y, x1.y, f1p[2*k2+1]);
            }
        }
        float f2a = fmaxf(hsum2(a0x) + hsum2(a0y), 0.f);
        float f2b = fmaxf(hsum2(a1x) + hsum2(a1y), 0.f);
        u64 f2lo = pack2(f2a, f2a);
        u64 f2hi = pack2(f2b, f2b);
        const u64* wra = sR1t + (2*jp) * 16;
        const u64* wrb = sR1t + (2*jp+1) * 16;
#pragma unroll
        for (int J = 0; J < 16; ++J) {
            fma2(r1acc[J], wra[J], f2lo);
            fma2(r1acc[J], wrb[J], f2hi);
        }
    }

    u64 racc = pack2(sscal[1], 0.f);
    const u64* r2w = (const u64*)sR2;
#pragma unroll
    for (int J = 0; J < 16; ++J) {
        float lo, hi; unpack2(r1acc[J], lo, hi);
        fma2(racc, r2w[J], pack2(fmaxf(lo, 0.f), fmaxf(hi, 0.f)));
    }
    float r = hsum2(racc);

    const int day = day_ids[b];
    float health[8];
#pragma unroll
    for (int i = 0; i < 8; ++i) health[i] = g_traj[day * 8 + i];
    float4 rv = ((const float4*)raw)[idx];
    float iphys = rv.x * 9.0f * (1.0f + 0.0005f * (rv.y - 0.5f));
    float rawD = sscal[0];
#pragma unroll
    for (int i = 0; i < 8; ++i) rawD = fmaf(health[i], shdw[i], rawD);
    float D = fsig(rawD);

    float ibase = D * iphys;
    out[(size_t)0 * NPOS + idx] = ibase + r;   // I_pred
    out[(size_t)1 * NPOS + idx] = iphys;       // I_phys
    out[(size_t)2 * NPOS + idx] = ibase;       // I_base
    out[(size_t)3 * NPOS + idx] = D;           // D
    out[(size_t)4 * NPOS + idx] = r;           // r
    float* ho = out + (size_t)5 * NPOS + (size_t)idx * 8;
#pragma unroll
    for (int i = 0; i < 8; ++i) ho[i] = health[i];  // health_seq
}

// ---------------- launch ----------------------------------------------------
extern "C" void kernel_launch(void* const* d_in, const int* in_sizes, int n_in,
                              void* d_out, int out_size)
{
    const float* X        = (const float*)d_in[0];
    const int*   day_ids  = (const int*)  d_in[1];
    const float* raw      = (const float*)d_in[2];
    const float* ih0      = (const float*)d_in[3];
    const float* oW1      = (const float*)d_in[4];
    const float* ob1      = (const float*)d_in[5];
    const float* oW2      = (const float*)d_in[6];
    const float* ob2      = (const float*)d_in[7];
    const float* oW3      = (const float*)d_in[8];
    const float* ob3      = (const float*)d_in[9];
    const float* Wih0     = (const float*)d_in[10];
    const float* Whh0     = (const float*)d_in[11];
    const float* bih0     = (const float*)d_in[12];
    const float* bhh0     = (const float*)d_in[13];
    const float* Wih1     = (const float*)d_in[14];
    const float* Whh1     = (const float*)d_in[15];
    const float* bih1     = (const float*)d_in[16];
    const float* bhh1     = (const float*)d_in[17];
    const float* hdw      = (const float*)d_in[18];
    const float* hdb      = (const float*)d_in[19];
    const float* fW1      = (const float*)d_in[20];
    const float* fb1      = (const float*)d_in[21];
    const float* fW2      = (const float*)d_in[22];
    const float* fb2      = (const float*)d_in[23];
    const float* rW1      = (const float*)d_in[24];
    const float* rb1      = (const float*)d_in[25];
    const float* rW2      = (const float*)d_in[26];
    const float* rb2      = (const float*)d_in[27];

    float* gin0;  cudaGetSymbolAddress((void**)&gin0, g_gin0);

    // Stage Whh0 into the coalesced layout.
    k_stage<<<16, 256>>>(Whh0);
    // L0 input projection (parallel GEMM, f32x2, 4 CTAs/SM).
    k_gates0<<<NPOS / 128, 256>>>(X, Wih0, bih0, bhh0, gin0);
    // Fused L0+L1 recurrence, k-split 512 threads + ODE as CTA 128: one wave.
    k_recfused<<<129, 512>>>(Wih1, Whh1, bih1, bhh1,
                             ih0, oW1, ob1, oW2, ob2, oW3, ob3);
    // Fusion stage A: feat1 (2 CTAs/SM, coalesced z).
    k_fusA<<<NPOS / 256, 256>>>(day_ids, raw, fW1, fb1);
    // Fusion stage B: feat2 -> residual -> outputs (2 CTAs/SM).
    k_fusB<<<NPOS / 256, 256>>>(day_ids, raw, hdw, hdb,
                                fW2, fb2, rW1, rb1, rW2, rb2,
                                (float*)d_out);
}

// round 12
// speedup vs baseline: 1.2126x; 1.2126x over previous
#include <cuda_runtime.h>
#include <cstdint>
#include <cstddef>

#define NBATCH 256
#define NT     2048
#define NFIN   32
#define NHID   64
#define NPOS   (NBATCH * NT)   // 524288

typedef unsigned long long u64;

// ---------------- scratch (static device globals: allocation-free) ----------
__device__ u64   g_env1t[(size_t)32 * NPOS];            // L1 output, pair-major [pair][idx]
__device__ float g_gin0[(size_t)NPOS * 256];            // L0 gate input-proj
__device__ float g_f1[(size_t)NPOS * NHID];             // fusion feat1 (transposed pairs)
__device__ float4 g_wh0s[8 * 16 * 32];                  // staged Whh0 (64 KB)
__device__ float g_traj[366 * 8];                       // ODE trajectory

// ---------------- fast activations (fp32, ~1e-6 rel err) -------------------
__device__ __forceinline__ float fsig(float x) {
    return __fdividef(1.0f, 1.0f + __expf(-x));
}
__device__ __forceinline__ float ftanh(float x) {
    float ax = fabsf(x);
    float e  = __expf(-2.0f * ax);
    float r  = __fdividef(1.0f - e, 1.0f + e);
    return copysignf(r, x);
}

// ---------------- packed f32x2 helpers --------------------------------------
__device__ __forceinline__ u64 pack2(float lo, float hi) {
    u64 r; asm("mov.b64 %0, {%1, %2};" : "=l"(r) : "f"(lo), "f"(hi)); return r;
}
__device__ __forceinline__ void fma2(u64& a, u64 w, u64 v) {
    asm("fma.rn.f32x2 %0, %1, %2, %0;" : "+l"(a) : "l"(w), "l"(v));
}
__device__ __forceinline__ float hsum2(u64 a) {
    float lo, hi; asm("mov.b64 {%0, %1}, %2;" : "=f"(lo), "=f"(hi) : "l"(a));
    return lo + hi;
}
__device__ __forceinline__ void unpack2(u64 a, float& lo, float& hi) {
    asm("mov.b64 {%0, %1}, %2;" : "=f"(lo), "=f"(hi) : "l"(a));
}

// ---------------- ODE body (runs as blockIdx == 128 of fused rec) ----------
__device__ void ode_body(int tid,
                         const float* __restrict__ h0,
                         const float* __restrict__ W1, const float* __restrict__ b1,
                         const float* __restrict__ W2, const float* __restrict__ b2,
                         const float* __restrict__ W3, const float* __restrict__ b3)
{
    __shared__ float sInp[12];
    __shared__ float sz1[64];
    __shared__ float sz2[64];
    __shared__ float sk[6][8];
    __shared__ float shh[8];
    __shared__ __align__(16) float sW3[8 * 64];
    __shared__ float sb3[8];

    float w1r[9];
    float w2r[64];
    float b1j = 0.f, b2j = 0.f;
    if (tid < 64) {
#pragma unroll
        for (int k = 0; k < 9; ++k) w1r[k] = W1[tid * 9 + k];
#pragma unroll
        for (int k = 0; k < 64; ++k) w2r[k] = W2[tid * 64 + k];
        b1j = b1[tid];
        b2j = b2[tid];
    }
    for (int i = tid; i < 8 * 64; i += 256) sW3[i] = W3[i];
    if (tid < 8) {
        sb3[tid] = b3[tid];
        shh[tid] = h0[tid];
        g_traj[tid] = h0[tid];
    }
    __syncthreads();

    const float dt = 1.0f / 365.0f;

    for (int d = 0; d < 365; ++d) {
        float t0 = (float)d * dt;
#pragma unroll 1
        for (int s = 0; s < 6; ++s) {
            if (tid < 8) {
                float v = shh[tid];
                if (s == 1) v += dt * (0.2f * sk[0][tid]);
                else if (s == 2) v += dt * ((3.f/40.f)*sk[0][tid] + (9.f/40.f)*sk[1][tid]);
                else if (s == 3) v += dt * ((44.f/45.f)*sk[0][tid] - (56.f/15.f)*sk[1][tid] + (32.f/9.f)*sk[2][tid]);
                else if (s == 4) v += dt * ((19372.f/6561.f)*sk[0][tid] - (25360.f/2187.f)*sk[1][tid]
                                          + (64448.f/6561.f)*sk[2][tid] - (212.f/729.f)*sk[3][tid]);
                else if (s == 5) v += dt * ((9017.f/3168.f)*sk[0][tid] - (355.f/33.f)*sk[1][tid]
                                          + (46732.f/5247.f)*sk[2][tid] + (49.f/176.f)*sk[3][tid]
                                          - (5103.f/18656.f)*sk[4][tid]);
                sInp[tid] = v;
            }
            if (tid == 8) {
                float cn;
                if (s == 0) cn = 0.0f;
                else if (s == 1) cn = 0.2f;
                else if (s == 2) cn = 0.3f;
                else if (s == 3) cn = 0.8f;
                else if (s == 4) cn = 8.f/9.f;
                else cn = 1.0f;
                sInp[8] = t0 + cn * dt;
            }
            __syncthreads();
            if (tid < 64) {
                float a = b1j;
#pragma unroll
                for (int k = 0; k < 9; ++k) a = fmaf(w1r[k], sInp[k], a);
                sz1[tid] = ftanh(a);
            }
            __syncthreads();
            if (tid < 64) {
                float a0 = b2j, a1 = 0.f, a2 = 0.f, a3 = 0.f;
#pragma unroll
                for (int k = 0; k < 64; k += 4) {
                    a0 = fmaf(w2r[k+0], sz1[k+0], a0);
                    a1 = fmaf(w2r[k+1], sz1[k+1], a1);
                    a2 = fmaf(w2r[k+2], sz1[k+2], a2);
                    a3 = fmaf(w2r[k+3], sz1[k+3], a3);
                }
                sz2[tid] = ftanh((a0 + a1) + (a2 + a3));
            }
            __syncthreads();
            if (tid < 8) {
                float a0 = sb3[tid], a1 = 0.f, a2 = 0.f, a3 = 0.f;
#pragma unroll
                for (int k = 0; k < 64; k += 4) {
                    a0 = fmaf(sW3[tid*64 + k+0], sz2[k+0], a0);
                    a1 = fmaf(sW3[tid*64 + k+1], sz2[k+1], a1);
                    a2 = fmaf(sW3[tid*64 + k+2], sz2[k+2], a2);
                    a3 = fmaf(sW3[tid*64 + k+3], sz2[k+3], a3);
                }
                sk[s][tid] = (a0 + a1) + (a2 + a3);
            }
            __syncthreads();
        }
        if (tid < 8) {
            float hn = shh[tid] + dt * ((35.f/384.f)   * sk[0][tid]
                                      + (500.f/1113.f) * sk[2][tid]
                                      + (125.f/192.f)  * sk[3][tid]
                                      - (2187.f/6784.f)* sk[4][tid]
                                      + (11.f/84.f)    * sk[5][tid]);
            shh[tid] = hn;
            g_traj[(d + 1) * 8 + tid] = hn;
        }
        __syncthreads();
    }
}

// ============================================================================
// Stage Whh0 into lane-coalesced layout.
// ============================================================================
__global__ void k_stage(const float* __restrict__ Whh0)
{
    int e = blockIdx.x * 256 + threadIdx.x;   // grid 16 x 256 = 4096
    int l  = e & 31;
    int kp = (e >> 5) & 15;
    int w  = e >> 9;
    int r  = (l >> 3) * 64 + (w << 3) + (l & 7);
    g_wh0s[e] = *(const float4*)(Whh0 + r * 64 + kp * 4);
}

// ============================================================================
// L0 gate input-projection GEMM (f32x2), 4 CTAs/SM.
// ============================================================================
__global__ __launch_bounds__(256, 4) void k_gates0(
    const float* __restrict__ X,
    const float* __restrict__ Wih,
    const float* __restrict__ bih, const float* __restrict__ bhh,
    float* __restrict__ gout)
{
    __shared__ __align__(16) float xs[128 * NFIN];      // 16 kB
    const int tid = threadIdx.x;
    const size_t pos0 = (size_t)blockIdx.x * 128;

    const float4* xg = (const float4*)(X + pos0 * NFIN);
    float4* xs4 = (float4*)xs;
#pragma unroll
    for (int i = 0; i < 4; ++i) xs4[tid + 256 * i] = xg[tid + 256 * i];

    u64 wrp[16];
    {
        const u64* wp = (const u64*)(Wih + tid * NFIN);
#pragma unroll
        for (int k = 0; k < 16; ++k) wrp[k] = wp[k];
    }
    const float bias = bih[tid] + bhh[tid];
    __syncthreads();

#pragma unroll 1
    for (int p = 0; p < 128; p += 2) {
        u64 a0 = pack2(bias, 0.f), a1 = pack2(bias, 0.f);
        const ulonglong2* x0 = (const ulonglong2*)(xs + (p+0) * NFIN);
        const ulonglong2* x1 = (const ulonglong2*)(xs + (p+1) * NFIN);
#pragma unroll
        for (int k2 = 0; k2 < 8; ++k2) {
            ulonglong2 v0 = x0[k2], v1 = x1[k2];
            fma2(a0, wrp[2*k2], v0.x); fma2(a0, wrp[2*k2+1], v0.y);
            fma2(a1, wrp[2*k2], v1.x); fma2(a1, wrp[2*k2+1], v1.y);
        }
        gout[(pos0 + p + 0) * 256 + tid] = hsum2(a0);
        gout[(pos0 + p + 1) * 256 + tid] = hsum2(a1);
    }
}

// ============================================================================
// Fused recurrence (PROVEN R8/R9 structure): 256 threads, 2 rows/CTA,
// 1 barrier/step, f32x2 dots, 128 CTAs (+ ODE at blockIdx 128): one wave.
// env1 stored transposed pair-major for coalesced fusA reads.
// ============================================================================
__global__ __launch_bounds__(256, 1) void k_recfused(
    const float* __restrict__ Wih1g, const float* __restrict__ Whh1g,
    const float* __restrict__ bih1g, const float* __restrict__ bhh1g,
    const float* __restrict__ h0ode,
    const float* __restrict__ oW1, const float* __restrict__ ob1,
    const float* __restrict__ oW2, const float* __restrict__ ob2,
    const float* __restrict__ oW3, const float* __restrict__ ob3)
{
    const int t = threadIdx.x;
    if (blockIdx.x == 128) {
        ode_body(t, h0ode, oW1, ob1, oW2, ob2, oW3, ob3);
        return;
    }
    const int w  = t >> 5, l = t & 31;
    const int gt = l >> 3;
    const int u  = (w << 3) | (l & 7);
    const int r  = gt * 64 + u;
    const int lb = l & 7;
    const unsigned FULL = 0xffffffffu;

    u64 wi1[32], wh1[32], ws[32];
    {
        const u64* p1 = (const u64*)(Wih1g + r * 64);
        const u64* p2 = (const u64*)(Whh1g + r * 64);
#pragma unroll
        for (int k = 0; k < 32; ++k) { wi1[k] = p1[k]; wh1[k] = p2[k]; }
        const char* wsbase = (const char*)(g_wh0s + (w * 16) * 32 + l);
#pragma unroll
        for (int kp = 0; kp < 16; ++kp) {
            ulonglong2 u2 = *(const ulonglong2*)(wsbase + (size_t)kp * 512);
            ws[2*kp] = u2.x; ws[2*kp+1] = u2.y;
        }
    }
    const float bias1 = bih1g[r] + bhh1g[r];

    __shared__ __align__(16) float hs0[2][2][NHID];
    __shared__ __align__(16) float hs1[2][2][NHID];
    ((float*)hs0)[t] = 0.0f;
    ((float*)hs1)[t] = 0.0f;

    const int b0 = blockIdx.x * 2;
    const float* gA = g_gin0 + (size_t)b0 * NT * 256;
    const float* gB = gA + (size_t)NT * 256;
    const int idxA0 = b0 * NT;
    const int idxB0 = idxA0 + NT;
    const bool isg = (gt == 2);

    float c0A = 0.f, c0B = 0.f, c1A = 0.f, c1B = 0.f;

    float gnA = gA[r],        gnB = gB[r];          // gin for step 0
    float gxA = gA[256 + r],  gxB = gB[256 + r];    // gin for step 1
    __syncthreads();

    // ---- s = 0: L0 only; h0[-1] = 0 so gate = gin0[0] ----
    {
        float actA = isg ? ftanh(gnA) : fsig(gnA);
        float actB = isg ? ftanh(gnB) : fsig(gnB);
        float iA = __shfl_sync(FULL, actA, lb);
        float gA_ = __shfl_sync(FULL, actA, lb + 16);
        float oA = __shfl_sync(FULL, actA, lb + 24);
        float iB = __shfl_sync(FULL, actB, lb);
        float gB_ = __shfl_sync(FULL, actB, lb + 16);
        float oB = __shfl_sync(FULL, actB, lb + 24);
        c0A = iA * gA_;
        c0B = iB * gB_;
        float hA = oA * ftanh(c0A);
        float hB = oB * ftanh(c0B);
        if (gt == 0) { hs0[1][0][u] = hA; hs0[1][1][u] = hB; }
        gnA = gxA; gnB = gxB;
        gxA = gA[512 + r]; gxB = gB[512 + r];        // gin for step 2
        __syncthreads();
    }

    // ---- main loop s = 1 .. NT-1 ----
#pragma unroll 1
    for (int s = 1; s < NT; ++s) {
        const int cur = s & 1;
        const float* h0A = hs0[cur][0];
        const float* h0B = hs0[cur][1];
        const float* h1A = hs1[cur][0];
        const float* h1B = hs1[cur][1];

        u64 a0 = pack2(gnA, 0.f),   a1 = 0;   // L0 row A
        u64 b0 = pack2(gnB, 0.f),   b1 = 0;   // L0 row B
        u64 q0 = pack2(bias1, 0.f), q1 = 0;   // L1 row A
        u64 s0 = pack2(bias1, 0.f), s1 = 0;   // L1 row B
#pragma unroll
        for (int k = 0; k < NHID; k += 4) {
            ulonglong2 vA = *(const ulonglong2*)(h0A + k);
            ulonglong2 vB = *(const ulonglong2*)(h0B + k);
            ulonglong2 uA = *(const ulonglong2*)(h1A + k);
            ulonglong2 uB = *(const ulonglong2*)(h1B + k);
            const int kk = k >> 1;
            fma2(q0, wi1[kk], vA.x);  fma2(q1, wi1[kk+1], vA.y);
            fma2(q0, wh1[kk], uA.x);  fma2(q1, wh1[kk+1], uA.y);
            fma2(s0, wi1[kk], vB.x);  fma2(s1, wi1[kk+1], vB.y);
            fma2(s0, wh1[kk], uB.x);  fma2(s1, wh1[kk+1], uB.y);
            fma2(a0, ws[kk], vA.x);   fma2(a1, ws[kk+1], vA.y);
            fma2(b0, ws[kk], vB.x);   fma2(b1, ws[kk+1], vB.y);
        }
        gnA = gxA; gnB = gxB;
        if (s + 2 < NT) {
            gxA = gA[(size_t)(s + 2) * 256 + r];
            gxB = gB[(size_t)(s + 2) * 256 + r];
        }

        float p0A = hsum2(a0) + hsum2(a1);
        float p0B = hsum2(b0) + hsum2(b1);
        float p1A = hsum2(q0) + hsum2(q1);
        float p1B = hsum2(s0) + hsum2(s1);
        float act0A = isg ? ftanh(p0A) : fsig(p0A);
        float act0B = isg ? ftanh(p0B) : fsig(p0B);
        float act1A = isg ? ftanh(p1A) : fsig(p1A);
        float act1B = isg ? ftanh(p1B) : fsig(p1B);

        float i0A = __shfl_sync(FULL, act0A, lb);
        float f0A = __shfl_sync(FULL, act0A, lb + 8);
        float g0A = __shfl_sync(FULL, act0A, lb + 16);
        float o0A = __shfl_sync(FULL, act0A, lb + 24);
        float i0B = __shfl_sync(FULL, act0B, lb);
        float f0B = __shfl_sync(FULL, act0B, lb + 8);
        float g0B = __shfl_sync(FULL, act0B, lb + 16);
        float o0B = __shfl_sync(FULL, act0B, lb + 24);
        float i1A = __shfl_sync(FULL, act1A, lb);
        float f1A = __shfl_sync(FULL, act1A, lb + 8);
        float g1A = __shfl_sync(FULL, act1A, lb + 16);
        float o1A = __shfl_sync(FULL, act1A, lb + 24);
        float i1B = __shfl_sync(FULL, act1B, lb);
        float f1B = __shfl_sync(FULL, act1B, lb + 8);
        float g1B = __shfl_sync(FULL, act1B, lb + 16);
        float o1B = __shfl_sync(FULL, act1B, lb + 24);

        c0A = f0A * c0A + i0A * g0A;
        c0B = f0B * c0B + i0B * g0B;
        c1A = f1A * c1A + i1A * g1A;
        c1B = f1B * c1B + i1B * g1B;
        float h0nA = o0A * ftanh(c0A);
        float h0nB = o0B * ftanh(c0B);
        float h1nA = o1A * ftanh(c1A);
        float h1nB = o1B * ftanh(c1B);

        // neighbor h1 for packed transposed env1 store
        float h1hA = __shfl_down_sync(FULL, h1nA, 1);
        float h1hB = __shfl_down_sync(FULL, h1nB, 1);

        if (gt == 0) {
            hs0[cur ^ 1][0][u] = h0nA;
            hs0[cur ^ 1][1][u] = h0nB;
            hs1[cur ^ 1][0][u] = h1nA;
            hs1[cur ^ 1][1][u] = h1nB;
            if (!(lb & 1)) {
                size_t p = (size_t)(u >> 1) * NPOS;
                g_env1t[p + idxA0 + (s - 1)] = pack2(h1nA, h1hA);
                g_env1t[p + idxB0 + (s - 1)] = pack2(h1nB, h1hB);
            }
        }
        __syncthreads();
    }

    // ---- s = NT: L1 only, computing step NT-1 ----
    {
        const int cur = NT & 1;   // 0
        const float* h0A = hs0[cur][0];
        const float* h0B = hs0[cur][1];
        const float* h1A = hs1[cur][0];
        const float* h1B = hs1[cur][1];
        u64 q0 = pack2(bias1, 0.f), q1 = 0;
        u64 s0 = pack2(bias1, 0.f), s1 = 0;
#pragma unroll
        for (int k = 0; k < NHID; k += 4) {
            ulonglong2 vA = *(const ulonglong2*)(h0A + k);
            ulonglong2 vB = *(const ulonglong2*)(h0B + k);
            ulonglong2 uA = *(const ulonglong2*)(h1A + k);
            ulonglong2 uB = *(const ulonglong2*)(h1B + k);
            const int kk = k >> 1;
            fma2(q0, wi1[kk], vA.x);  fma2(q1, wi1[kk+1], vA.y);
            fma2(q0, wh1[kk], uA.x);  fma2(q1, wh1[kk+1], uA.y);
            fma2(s0, wi1[kk], vB.x);  fma2(s1, wi1[kk+1], vB.y);
            fma2(s0, wh1[kk], uB.x);  fma2(s1, wh1[kk+1], uB.y);
        }
        float p1A = hsum2(q0) + hsum2(q1);
        float p1B = hsum2(s0) + hsum2(s1);
        float act1A = isg ? ftanh(p1A) : fsig(p1A);
        float act1B = isg ? ftanh(p1B) : fsig(p1B);

        float i1A = __shfl_sync(FULL, act1A, lb);
        float f1A = __shfl_sync(FULL, act1A, lb + 8);
        float g1A = __shfl_sync(FULL, act1A, lb + 16);
        float o1A = __shfl_sync(FULL, act1A, lb + 24);
        float i1B = __shfl_sync(FULL, act1B, lb);
        float f1B = __shfl_sync(FULL, act1B, lb + 8);
        float g1B = __shfl_sync(FULL, act1B, lb + 16);
        float o1B = __shfl_sync(FULL, act1B, lb + 24);

        c1A = f1A * c1A + i1A * g1A;
        c1B = f1B * c1B + i1B * g1B;
        float h1nA = o1A * ftanh(c1A);
        float h1nB = o1B * ftanh(c1B);
        float h1hA = __shfl_down_sync(FULL, h1nA, 1);
        float h1hB = __shfl_down_sync(FULL, h1nB, 1);
        if (gt == 0 && !(lb & 1)) {
            size_t p = (size_t)(u >> 1) * NPOS;
            g_env1t[p + idxA0 + (NT - 1)] = pack2(h1nA, h1hA);
            g_env1t[p + idxB0 + (NT - 1)] = pack2(h1nB, h1hB);
        }
    }
}

// ============================================================================
// Fusion stage A: feat1 = relu(fus_W1 @ z + fb1). 2 CTAs/SM.
// z loads fully coalesced from transposed env1; 4 accumulator chains.
// ============================================================================
__global__ __launch_bounds__(256, 2) void k_fusA(
    const int*   __restrict__ day_ids,
    const float* __restrict__ raw,
    const float* __restrict__ fW1, const float* __restrict__ fb1)
{
    const int tid = threadIdx.x;
    __shared__ __align__(16) float sW1[64 * 76];   // fus_W1 padded 73 -> 76
    __shared__ float sb1[64];

    for (int i = tid; i < 64 * 76; i += 256) {
        int j = i / 76, k = i - j * 76;
        sW1[i] = (k < 73) ? fW1[j * 73 + k] : 0.0f;
    }
    if (tid < 64) sb1[tid] = fb1[tid];
    __syncthreads();

    const int idx = blockIdx.x * 256 + tid;
    const int b = idx >> 11;

    u64 zp[38];
#pragma unroll
    for (int j = 0; j < 32; ++j)
        zp[j] = g_env1t[(size_t)j * NPOS + idx];   // coalesced
    const int day = day_ids[b];
#pragma unroll
    for (int i = 0; i < 4; ++i)
        zp[32 + i] = pack2(g_traj[day * 8 + 2*i], g_traj[day * 8 + 2*i + 1]);

    float4 rv = ((const float4*)raw)[idx];
    float iphys = rv.x * 9.0f * (1.0f + 0.0005f * (rv.y - 0.5f));
    zp[36] = pack2(iphys, 0.f);
    zp[37] = 0;

    u64* f1out = (u64*)g_f1;
#pragma unroll 1
    for (int j = 0; j < 64; j += 2) {
        u64 a0x = pack2(sb1[j], 0.f),   a0y = 0;
        u64 a1x = pack2(sb1[j+1], 0.f), a1y = 0;
        const ulonglong2* w0 = (const ulonglong2*)(sW1 + (j+0) * 76);
        const ulonglong2* w1 = (const ulonglong2*)(sW1 + (j+1) * 76);
#pragma unroll
        for (int k2 = 0; k2 < 19; ++k2) {
            ulonglong2 x0 = w0[k2], x1 = w1[k2];
            if (k2 < 10) {
                fma2(a0x, x0.x, zp[2*k2]); fma2(a0x, x0.y, zp[2*k2+1]);
                fma2(a1x, x1.x, zp[2*k2]); fma2(a1x, x1.y, zp[2*k2+1]);
            } else {
                fma2(a0y, x0.x, zp[2*k2]); fma2(a0y, x0.y, zp[2*k2+1]);
                fma2(a1y, x1.x, zp[2*k2]); fma2(a1y, x1.y, zp[2*k2+1]);
            }
        }
        f1out[(size_t)(j >> 1) * NPOS + idx] =
            pack2(fmaxf(hsum2(a0x) + hsum2(a0y), 0.f),
                  fmaxf(hsum2(a1x) + hsum2(a1y), 0.f));
    }
}

// ============================================================================
// Fusion stage B: f1 -> f2 -> r1 -> outputs. 2 CTAs/SM; 4 chains in f2 dots.
// ============================================================================
__global__ __launch_bounds__(256, 2) void k_fusB(
    const int*   __restrict__ day_ids,
    const float* __restrict__ raw,
    const float* __restrict__ hdw, const float* __restrict__ hdb,
    const float* __restrict__ fW2, const float* __restrict__ fb2,
    const float* __restrict__ rW1, const float* __restrict__ rb1,
    const float* __restrict__ rW2, const float* __restrict__ rb2,
    float* __restrict__ out)
{
    const int tid = threadIdx.x;

    __shared__ __align__(16) float sW2[64 * 64];    // 16 kB (row-major)
    __shared__ __align__(16) u64   sR1t[64 * 16];   // 8 kB: [k][J]
    __shared__ __align__(16) float sR2[32];
    __shared__ float sb2[64], srb1[32];
    __shared__ float shdw[8];
    __shared__ float sscal[2];

    for (int i = tid; i < 64 * 64; i += 256) sW2[i] = fW2[i];
    for (int i = tid; i < 64 * 16; i += 256) {
        int k = i >> 4, J = i & 15;
        sR1t[i] = pack2(rW1[(2*J) * 64 + k], rW1[(2*J+1) * 64 + k]);
    }
    if (tid < 64) sb2[tid] = fb2[tid];
    if (tid < 32) { sR2[tid] = rW2[tid]; srb1[tid] = rb1[tid]; }
    if (tid < 8)  shdw[tid] = hdw[tid];
    if (tid == 0) { sscal[0] = hdb[0]; sscal[1] = rb2[0]; }
    __syncthreads();

    const int idx = blockIdx.x * 256 + tid;
    const int b = idx >> 11;

    u64 f1p[32];
    const u64* f1in = (const u64*)g_f1;
#pragma unroll
    for (int k2 = 0; k2 < 32; ++k2)
        f1p[k2] = f1in[(size_t)k2 * NPOS + idx];

    u64 r1acc[16];
#pragma unroll
    for (int J = 0; J < 16; ++J) r1acc[J] = pack2(srb1[2*J], srb1[2*J+1]);

#pragma unroll 1
    for (int jp = 0; jp < 32; ++jp) {
        u64 a0x = pack2(sb2[2*jp], 0.f),   a0y = 0;
        u64 a1x = pack2(sb2[2*jp+1], 0.f), a1y = 0;
        const ulonglong2* w0 = (const ulonglong2*)(sW2 + (2*jp+0) * 64);
        const ulonglong2* w1 = (const ulonglong2*)(sW2 + (2*jp+1) * 64);
#pragma unroll
        for (int k2 = 0; k2 < 16; ++k2) {
            ulonglong2 x0 = w0[k2], x1 = w1[k2];
            if (k2 < 8) {
                fma2(a0x, x0.x, f1p[2*k2]); fma2(a0x, x0.y, f1p[2*k2+1]);
                fma2(a1x, x1.x, f1p[2*k2]); fma2(a1x, x1.y, f1p[2*k2+1]);
            } else {
                fma2(a0y, x0.x, f1p[2*k2]); fma2(a0y, x0.y, f1p[2*k2+1]);
                fma2(a1y, x1.x, f1p[2*k2]); fma2(a1y, x1.y, f1p[2*k2+1]);
            }
        }
        float f2a = fmaxf(hsum2(a0x) + hsum2(a0y), 0.f);
        float f2b = fmaxf(hsum2(a1x) + hsum2(a1y), 0.f);
        u64 f2lo = pack2(f2a, f2a);
        u64 f2hi = pack2(f2b, f2b);
        const u64* wra = sR1t + (2*jp) * 16;
        const u64* wrb = sR1t + (2*jp+1) * 16;
#pragma unroll
        for (int J = 0; J < 16; ++J) {
            fma2(r1acc[J], wra[J], f2lo);
            fma2(r1acc[J], wrb[J], f2hi);
        }
    }

    u64 racc = pack2(sscal[1], 0.f);
    const u64* r2w = (const u64*)sR2;
#pragma unroll
    for (int J = 0; J < 16; ++J) {
        float lo, hi; unpack2(r1acc[J], lo, hi);
        fma2(racc, r2w[J], pack2(fmaxf(lo, 0.f), fmaxf(hi, 0.f)));
    }
    float r = hsum2(racc);

    const int day = day_ids[b];
    float health[8];
#pragma unroll
    for (int i = 0; i < 8; ++i) health[i] = g_traj[day * 8 + i];
    float4 rv = ((const float4*)raw)[idx];
    float iphys = rv.x * 9.0f * (1.0f + 0.0005f * (rv.y - 0.5f));
    float rawD = sscal[0];
#pragma unroll
    for (int i = 0; i < 8; ++i) rawD = fmaf(health[i], shdw[i], rawD);
    float D = fsig(rawD);

    float ibase = D * iphys;
    out[(size_t)0 * NPOS + idx] = ibase + r;   // I_pred
    out[(size_t)1 * NPOS + idx] = iphys;       // I_phys
    out[(size_t)2 * NPOS + idx] = ibase;       // I_base
    out[(size_t)3 * NPOS + idx] = D;           // D
    out[(size_t)4 * NPOS + idx] = r;           // r
    float* ho = out + (size_t)5 * NPOS + (size_t)idx * 8;
#pragma unroll
    for (int i = 0; i < 8; ++i) ho[i] = health[i];  // health_seq
}

// ---------------- launch ----------------------------------------------------
extern "C" void kernel_launch(void* const* d_in, const int* in_sizes, int n_in,
                              void* d_out, int out_size)
{
    const float* X        = (const float*)d_in[0];
    const int*   day_ids  = (const int*)  d_in[1];
    const float* raw      = (const float*)d_in[2];
    const float* ih0      = (const float*)d_in[3];
    const float* oW1      = (const float*)d_in[4];
    const float* ob1      = (const float*)d_in[5];
    const float* oW2      = (const float*)d_in[6];
    const float* ob2      = (const float*)d_in[7];
    const float* oW3      = (const float*)d_in[8];
    const float* ob3      = (const float*)d_in[9];
    const float* Wih0     = (const float*)d_in[10];
    const float* Whh0     = (const float*)d_in[11];
    const float* bih0     = (const float*)d_in[12];
    const float* bhh0     = (const float*)d_in[13];
    const float* Wih1     = (const float*)d_in[14];
    const float* Whh1     = (const float*)d_in[15];
    const float* bih1     = (const float*)d_in[16];
    const float* bhh1     = (const float*)d_in[17];
    const float* hdw      = (const float*)d_in[18];
    const float* hdb      = (const float*)d_in[19];
    const float* fW1      = (const float*)d_in[20];
    const float* fb1      = (const float*)d_in[21];
    const float* fW2      = (const float*)d_in[22];
    const float* fb2      = (const float*)d_in[23];
    const float* rW1      = (const float*)d_in[24];
    const float* rb1      = (const float*)d_in[25];
    const float* rW2      = (const float*)d_in[26];
    const float* rb2      = (const float*)d_in[27];

    float* gin0;  cudaGetSymbolAddress((void**)&gin0, g_gin0);

    // Stage Whh0 into the coalesced layout.
    k_stage<<<16, 256>>>(Whh0);
    // L0 input projection (parallel GEMM, f32x2, 4 CTAs/SM).
    k_gates0<<<NPOS / 128, 256>>>(X, Wih0, bih0, bhh0, gin0);
    // Fused L0+L1 recurrence (proven 256-thread structure) + ODE as CTA 128.
    k_recfused<<<129, 256>>>(Wih1, Whh1, bih1, bhh1,
                             ih0, oW1, ob1, oW2, ob2, oW3, ob3);
    // Fusion stage A: feat1 (2 CTAs/SM, coalesced z).
    k_fusA<<<NPOS / 256, 256>>>(day_ids, raw, fW1, fb1);
    // Fusion stage B: feat2 -> residual -> outputs (2 CTAs/SM).
    k_fusB<<<NPOS / 256, 256>>>(day_ids, raw, hdw, hdb,
                                fW2, fb2, rW1, rb1, rW2, rb2,
                                (float*)d_out);
}

// round 13
// speedup vs baseline: 1.3565x; 1.1187x over previous
#include <cuda_runtime.h>
#include <cstdint>
#include <cstddef>

#define NBATCH 256
#define NT     2048
#define NFIN   32
#define NHID   64
#define NPOS   (NBATCH * NT)   // 524288

typedef unsigned long long u64;

// ---------------- scratch (static device globals: allocation-free) ----------
__device__ float g_env1[(size_t)NBATCH * NT * NHID];    // layer-1 LSTM output
__device__ float g_gin0[(size_t)NPOS * 256];            // L0 gate input-proj
__device__ float g_f1[(size_t)NPOS * NHID];             // fusion feat1 (transposed pairs)
__device__ float4 g_wh0s[8 * 16 * 32];                  // staged Whh0 (64 KB)
__device__ float g_traj[366 * 8];                       // ODE trajectory

// ---------------- fast activations (fp32, ~1e-6 rel err) -------------------
__device__ __forceinline__ float fsig(float x) {
    return __fdividef(1.0f, 1.0f + __expf(-x));
}
__device__ __forceinline__ float ftanh(float x) {
    float ax = fabsf(x);
    float e  = __expf(-2.0f * ax);
    float r  = __fdividef(1.0f - e, 1.0f + e);
    return copysignf(r, x);
}
// branch-free gate activation: aS=1,aO=0 -> sigmoid; aS=2,aO=-1 -> tanh
__device__ __forceinline__ float actfn(float x, float aS, float aO) {
    return fmaf(aS, fsig(aS * x), aO);
}
// tanh via sigmoid (branch-free, short)
__device__ __forceinline__ float ftanh2(float x) {
    return fmaf(2.0f, fsig(2.0f * x), -1.0f);
}

// ---------------- packed f32x2 helpers --------------------------------------
__device__ __forceinline__ u64 pack2(float lo, float hi) {
    u64 r; asm("mov.b64 %0, {%1, %2};" : "=l"(r) : "f"(lo), "f"(hi)); return r;
}
__device__ __forceinline__ void fma2(u64& a, u64 w, u64 v) {
    asm("fma.rn.f32x2 %0, %1, %2, %0;" : "+l"(a) : "l"(w), "l"(v));
}
__device__ __forceinline__ float hsum2(u64 a) {
    float lo, hi; asm("mov.b64 {%0, %1}, %2;" : "=f"(lo), "=f"(hi) : "l"(a));
    return lo + hi;
}
__device__ __forceinline__ void unpack2(u64 a, float& lo, float& hi) {
    asm("mov.b64 {%0, %1}, %2;" : "=f"(lo), "=f"(hi) : "l"(a));
}

// ---------------- ODE body (runs as blockIdx == 128 of fused rec) ----------
__device__ void ode_body(int tid,
                         const float* __restrict__ h0,
                         const float* __restrict__ W1, const float* __restrict__ b1,
                         const float* __restrict__ W2, const float* __restrict__ b2,
                         const float* __restrict__ W3, const float* __restrict__ b3)
{
    __shared__ float sInp[12];
    __shared__ float sz1[64];
    __shared__ float sz2[64];
    __shared__ float sk[6][8];
    __shared__ float shh[8];
    __shared__ __align__(16) float sW3[8 * 64];
    __shared__ float sb3[8];

    float w1r[9];
    float w2r[64];
    float b1j = 0.f, b2j = 0.f;
    if (tid < 64) {
#pragma unroll
        for (int k = 0; k < 9; ++k) w1r[k] = W1[tid * 9 + k];
#pragma unroll
        for (int k = 0; k < 64; ++k) w2r[k] = W2[tid * 64 + k];
        b1j = b1[tid];
        b2j = b2[tid];
    }
    for (int i = tid; i < 8 * 64; i += 256) sW3[i] = W3[i];
    if (tid < 8) {
        sb3[tid] = b3[tid];
        shh[tid] = h0[tid];
        g_traj[tid] = h0[tid];
    }
    __syncthreads();

    const float dt = 1.0f / 365.0f;

    for (int d = 0; d < 365; ++d) {
        float t0 = (float)d * dt;
#pragma unroll 1
        for (int s = 0; s < 6; ++s) {
            if (tid < 8) {
                float v = shh[tid];
                if (s == 1) v += dt * (0.2f * sk[0][tid]);
                else if (s == 2) v += dt * ((3.f/40.f)*sk[0][tid] + (9.f/40.f)*sk[1][tid]);
                else if (s == 3) v += dt * ((44.f/45.f)*sk[0][tid] - (56.f/15.f)*sk[1][tid] + (32.f/9.f)*sk[2][tid]);
                else if (s == 4) v += dt * ((19372.f/6561.f)*sk[0][tid] - (25360.f/2187.f)*sk[1][tid]
                                          + (64448.f/6561.f)*sk[2][tid] - (212.f/729.f)*sk[3][tid]);
                else if (s == 5) v += dt * ((9017.f/3168.f)*sk[0][tid] - (355.f/33.f)*sk[1][tid]
                                          + (46732.f/5247.f)*sk[2][tid] + (49.f/176.f)*sk[3][tid]
                                          - (5103.f/18656.f)*sk[4][tid]);
                sInp[tid] = v;
            }
            if (tid == 8) {
                float cn;
                if (s == 0) cn = 0.0f;
                else if (s == 1) cn = 0.2f;
                else if (s == 2) cn = 0.3f;
                else if (s == 3) cn = 0.8f;
                else if (s == 4) cn = 8.f/9.f;
                else cn = 1.0f;
                sInp[8] = t0 + cn * dt;
            }
            __syncthreads();
            if (tid < 64) {
                float a = b1j;
#pragma unroll
                for (int k = 0; k < 9; ++k) a = fmaf(w1r[k], sInp[k], a);
                sz1[tid] = ftanh(a);
            }
            __syncthreads();
            if (tid < 64) {
                float a0 = b2j, a1 = 0.f, a2 = 0.f, a3 = 0.f;
#pragma unroll
                for (int k = 0; k < 64; k += 4) {
                    a0 = fmaf(w2r[k+0], sz1[k+0], a0);
                    a1 = fmaf(w2r[k+1], sz1[k+1], a1);
                    a2 = fmaf(w2r[k+2], sz1[k+2], a2);
                    a3 = fmaf(w2r[k+3], sz1[k+3], a3);
                }
                sz2[tid] = ftanh((a0 + a1) + (a2 + a3));
            }
            __syncthreads();
            if (tid < 8) {
                float a0 = sb3[tid], a1 = 0.f, a2 = 0.f, a3 = 0.f;
#pragma unroll
                for (int k = 0; k < 64; k += 4) {
                    a0 = fmaf(sW3[tid*64 + k+0], sz2[k+0], a0);
                    a1 = fmaf(sW3[tid*64 + k+1], sz2[k+1], a1);
                    a2 = fmaf(sW3[tid*64 + k+2], sz2[k+2], a2);
                    a3 = fmaf(sW3[tid*64 + k+3], sz2[k+3], a3);
                }
                sk[s][tid] = (a0 + a1) + (a2 + a3);
            }
            __syncthreads();
        }
        if (tid < 8) {
            float hn = shh[tid] + dt * ((35.f/384.f)   * sk[0][tid]
                                      + (500.f/1113.f) * sk[2][tid]
                                      + (125.f/192.f)  * sk[3][tid]
                                      - (2187.f/6784.f)* sk[4][tid]
                                      + (11.f/84.f)    * sk[5][tid]);
            shh[tid] = hn;
            g_traj[(d + 1) * 8 + tid] = hn;
        }
        __syncthreads();
    }
}

// ============================================================================
// Stage Whh0 into lane-coalesced layout.
// ============================================================================
__global__ void k_stage(const float* __restrict__ Whh0)
{
    int e = blockIdx.x * 256 + threadIdx.x;   // grid 16 x 256 = 4096
    int l  = e & 31;
    int kp = (e >> 5) & 15;
    int w  = e >> 9;
    int r  = (l >> 3) * 64 + (w << 3) + (l & 7);
    g_wh0s[e] = *(const float4*)(Whh0 + r * 64 + kp * 4);
}

// ============================================================================
// L0 gate input-projection GEMM (f32x2), 4 CTAs/SM.
// ============================================================================
__global__ __launch_bounds__(256, 4) void k_gates0(
    const float* __restrict__ X,
    const float* __restrict__ Wih,
    const float* __restrict__ bih, const float* __restrict__ bhh,
    float* __restrict__ gout)
{
    __shared__ __align__(16) float xs[128 * NFIN];      // 16 kB
    const int tid = threadIdx.x;
    const size_t pos0 = (size_t)blockIdx.x * 128;

    const float4* xg = (const float4*)(X + pos0 * NFIN);
    float4* xs4 = (float4*)xs;
#pragma unroll
    for (int i = 0; i < 4; ++i) xs4[tid + 256 * i] = xg[tid + 256 * i];

    u64 wrp[16];
    {
        const u64* wp = (const u64*)(Wih + tid * NFIN);
#pragma unroll
        for (int k = 0; k < 16; ++k) wrp[k] = wp[k];
    }
    const float bias = bih[tid] + bhh[tid];
    __syncthreads();

#pragma unroll 1
    for (int p = 0; p < 128; p += 2) {
        u64 a0 = pack2(bias, 0.f), a1 = pack2(bias, 0.f);
        const ulonglong2* x0 = (const ulonglong2*)(xs + (p+0) * NFIN);
        const ulonglong2* x1 = (const ulonglong2*)(xs + (p+1) * NFIN);
#pragma unroll
        for (int k2 = 0; k2 < 8; ++k2) {
            ulonglong2 v0 = x0[k2], v1 = x1[k2];
            fma2(a0, wrp[2*k2], v0.x); fma2(a0, wrp[2*k2+1], v0.y);
            fma2(a1, wrp[2*k2], v1.x); fma2(a1, wrp[2*k2+1], v1.y);
        }
        gout[(pos0 + p + 0) * 256 + tid] = hsum2(a0);
        gout[(pos0 + p + 1) * 256 + tid] = hsum2(a1);
    }
}

// ============================================================================
// Fused recurrence (R8 champion structure): 256 threads, 2 rows/CTA,
// 1 barrier/step, f32x2 dots, row-major env1 store, 128 CTAs (+ ODE at 128).
// NEW: branch-free unified gate activation (tanh = 2*sigmoid(2x)-1).
// ============================================================================
__global__ __launch_bounds__(256, 1) void k_recfused(
    const float* __restrict__ Wih1g, const float* __restrict__ Whh1g,
    const float* __restrict__ bih1g, const float* __restrict__ bhh1g,
    const float* __restrict__ h0ode,
    const float* __restrict__ oW1, const float* __restrict__ ob1,
    const float* __restrict__ oW2, const float* __restrict__ ob2,
    const float* __restrict__ oW3, const float* __restrict__ ob3)
{
    const int t = threadIdx.x;
    if (blockIdx.x == 128) {
        ode_body(t, h0ode, oW1, ob1, oW2, ob2, oW3, ob3);
        return;
    }
    const int w  = t >> 5, l = t & 31;
    const int gt = l >> 3;
    const int u  = (w << 3) | (l & 7);
    const int r  = gt * 64 + u;
    const int lb = l & 7;
    const unsigned FULL = 0xffffffffu;

    // unified activation constants: gate 2 (g) is tanh, others sigmoid
    const float aS = (gt == 2) ? 2.0f : 1.0f;
    const float aO = (gt == 2) ? -1.0f : 0.0f;

    u64 wi1[32], wh1[32], ws[32];
    {
        const u64* p1 = (const u64*)(Wih1g + r * 64);
        const u64* p2 = (const u64*)(Whh1g + r * 64);
#pragma unroll
        for (int k = 0; k < 32; ++k) { wi1[k] = p1[k]; wh1[k] = p2[k]; }
        const char* wsbase = (const char*)(g_wh0s + (w * 16) * 32 + l);
#pragma unroll
        for (int kp = 0; kp < 16; ++kp) {
            ulonglong2 u2 = *(const ulonglong2*)(wsbase + (size_t)kp * 512);
            ws[2*kp] = u2.x; ws[2*kp+1] = u2.y;
        }
    }
    const float bias1 = bih1g[r] + bhh1g[r];

    __shared__ __align__(16) float hs0[2][2][NHID];
    __shared__ __align__(16) float hs1[2][2][NHID];
    ((float*)hs0)[t] = 0.0f;
    ((float*)hs1)[t] = 0.0f;

    const int b0 = blockIdx.x * 2;
    const float* gA = g_gin0 + (size_t)b0 * NT * 256;
    const float* gB = gA + (size_t)NT * 256;
    float* e0 = g_env1 + (size_t)b0 * NT * NHID;
    float* e1 = e0 + (size_t)NT * NHID;

    float c0A = 0.f, c0B = 0.f, c1A = 0.f, c1B = 0.f;

    float gnA = gA[r],        gnB = gB[r];          // gin for step 0
    float gxA = gA[256 + r],  gxB = gB[256 + r];    // gin for step 1
    __syncthreads();

    // ---- s = 0: L0 only; h0[-1] = 0 so gate = gin0[0] ----
    {
        float actA = actfn(gnA, aS, aO);
        float actB = actfn(gnB, aS, aO);
        float iA = __shfl_sync(FULL, actA, lb);
        float gA_ = __shfl_sync(FULL, actA, lb + 16);
        float oA = __shfl_sync(FULL, actA, lb + 24);
        float iB = __shfl_sync(FULL, actB, lb);
        float gB_ = __shfl_sync(FULL, actB, lb + 16);
        float oB = __shfl_sync(FULL, actB, lb + 24);
        c0A = iA * gA_;
        c0B = iB * gB_;
        float hA = oA * ftanh2(c0A);
        float hB = oB * ftanh2(c0B);
        if (gt == 0) { hs0[1][0][u] = hA; hs0[1][1][u] = hB; }
        gnA = gxA; gnB = gxB;
        gxA = gA[512 + r]; gxB = gB[512 + r];        // gin for step 2
        __syncthreads();
    }

    // ---- main loop s = 1 .. NT-1 ----
#pragma unroll 1
    for (int s = 1; s < NT; ++s) {
        const int cur = s & 1;
        const float* h0A = hs0[cur][0];
        const float* h0B = hs0[cur][1];
        const float* h1A = hs1[cur][0];
        const float* h1B = hs1[cur][1];

        u64 a0 = pack2(gnA, 0.f),   a1 = 0;   // L0 row A
        u64 b0 = pack2(gnB, 0.f),   b1 = 0;   // L0 row B
        u64 q0 = pack2(bias1, 0.f), q1 = 0;   // L1 row A
        u64 s0 = pack2(bias1, 0.f), s1 = 0;   // L1 row B
#pragma unroll
        for (int k = 0; k < NHID; k += 4) {
            ulonglong2 vA = *(const ulonglong2*)(h0A + k);
            ulonglong2 vB = *(const ulonglong2*)(h0B + k);
            ulonglong2 uA = *(const ulonglong2*)(h1A + k);
            ulonglong2 uB = *(const ulonglong2*)(h1B + k);
            const int kk = k >> 1;
            fma2(q0, wi1[kk], vA.x);  fma2(q1, wi1[kk+1], vA.y);
            fma2(q0, wh1[kk], uA.x);  fma2(q1, wh1[kk+1], uA.y);
            fma2(s0, wi1[kk], vB.x);  fma2(s1, wi1[kk+1], vB.y);
            fma2(s0, wh1[kk], uB.x);  fma2(s1, wh1[kk+1], uB.y);
            fma2(a0, ws[kk], vA.x);   fma2(a1, ws[kk+1], vA.y);
            fma2(b0, ws[kk], vB.x);   fma2(b1, ws[kk+1], vB.y);
        }
        gnA = gxA; gnB = gxB;
        if (s + 2 < NT) {
            gxA = gA[(size_t)(s + 2) * 256 + r];
            gxB = gB[(size_t)(s + 2) * 256 + r];
        }

        float p0A = hsum2(a0) + hsum2(a1);
        float p0B = hsum2(b0) + hsum2(b1);
        float p1A = hsum2(q0) + hsum2(q1);
        float p1B = hsum2(s0) + hsum2(s1);
        float act0A = actfn(p0A, aS, aO);
        float act0B = actfn(p0B, aS, aO);
        float act1A = actfn(p1A, aS, aO);
        float act1B = actfn(p1B, aS, aO);

        float i0A = __shfl_sync(FULL, act0A, lb);
        float f0A = __shfl_sync(FULL, act0A, lb + 8);
        float g0A = __shfl_sync(FULL, act0A, lb + 16);
        float o0A = __shfl_sync(FULL, act0A, lb + 24);
        float i0B = __shfl_sync(FULL, act0B, lb);
        float f0B = __shfl_sync(FULL, act0B, lb + 8);
        float g0B = __shfl_sync(FULL, act0B, lb + 16);
        float o0B = __shfl_sync(FULL, act0B, lb + 24);
        float i1A = __shfl_sync(FULL, act1A, lb);
        float f1A = __shfl_sync(FULL, act1A, lb + 8);
        float g1A = __shfl_sync(FULL, act1A, lb + 16);
        float o1A = __shfl_sync(FULL, act1A, lb + 24);
        float i1B = __shfl_sync(FULL, act1B, lb);
        float f1B = __shfl_sync(FULL, act1B, lb + 8);
        float g1B = __shfl_sync(FULL, act1B, lb + 16);
        float o1B = __shfl_sync(FULL, act1B, lb + 24);

        c0A = f0A * c0A + i0A * g0A;
        c0B = f0B * c0B + i0B * g0B;
        c1A = f1A * c1A + i1A * g1A;
        c1B = f1B * c1B + i1B * g1B;
        float h0nA = o0A * ftanh2(c0A);
        float h0nB = o0B * ftanh2(c0B);
        float h1nA = o1A * ftanh2(c1A);
        float h1nB = o1B * ftanh2(c1B);

        if (gt == 0) {
            hs0[cur ^ 1][0][u] = h0nA;
            hs0[cur ^ 1][1][u] = h0nB;
            hs1[cur ^ 1][0][u] = h1nA;
            hs1[cur ^ 1][1][u] = h1nB;
            e0[(size_t)(s - 1) * NHID + u] = h1nA;
            e1[(size_t)(s - 1) * NHID + u] = h1nB;
        }
        __syncthreads();
    }

    // ---- s = NT: L1 only, computing step NT-1 ----
    {
        const int cur = NT & 1;   // 0
        const float* h0A = hs0[cur][0];
        const float* h0B = hs0[cur][1];
        const float* h1A = hs1[cur][0];
        const float* h1B = hs1[cur][1];
        u64 q0 = pack2(bias1, 0.f), q1 = 0;
        u64 s0 = pack2(bias1, 0.f), s1 = 0;
#pragma unroll
        for (int k = 0; k < NHID; k += 4) {
            ulonglong2 vA = *(const ulonglong2*)(h0A + k);
            ulonglong2 vB = *(const ulonglong2*)(h0B + k);
            ulonglong2 uA = *(const ulonglong2*)(h1A + k);
            ulonglong2 uB = *(const ulonglong2*)(h1B + k);
            const int kk = k >> 1;
            fma2(q0, wi1[kk], vA.x);  fma2(q1, wi1[kk+1], vA.y);
            fma2(q0, wh1[kk], uA.x);  fma2(q1, wh1[kk+1], uA.y);
            fma2(s0, wi1[kk], vB.x);  fma2(s1, wi1[kk+1], vB.y);
            fma2(s0, wh1[kk], uB.x);  fma2(s1, wh1[kk+1], uB.y);
        }
        float p1A = hsum2(q0) + hsum2(q1);
        float p1B = hsum2(s0) + hsum2(s1);
        float act1A = actfn(p1A, aS, aO);
        float act1B = actfn(p1B, aS, aO);

        float i1A = __shfl_sync(FULL, act1A, lb);
        float f1A = __shfl_sync(FULL, act1A, lb + 8);
        float g1A = __shfl_sync(FULL, act1A, lb + 16);
        float o1A = __shfl_sync(FULL, act1A, lb + 24);
        float i1B = __shfl_sync(FULL, act1B, lb);
        float f1B = __shfl_sync(FULL, act1B, lb + 8);
        float g1B = __shfl_sync(FULL, act1B, lb + 16);
        float o1B = __shfl_sync(FULL, act1B, lb + 24);

        c1A = f1A * c1A + i1A * g1A;
        c1B = f1B * c1B + i1B * g1B;
        float h1nA = o1A * ftanh2(c1A);
        float h1nB = o1B * ftanh2(c1B);
        if (gt == 0) {
            e0[(size_t)(NT - 1) * NHID + u] = h1nA;
            e1[(size_t)(NT - 1) * NHID + u] = h1nB;
        }
    }
}

// ============================================================================
// Fusion stage A: feat1 = relu(fus_W1 @ z + fb1). 2 CTAs/SM, 4 acc chains.
// ============================================================================
__global__ __launch_bounds__(256, 2) void k_fusA(
    const int*   __restrict__ day_ids,
    const float* __restrict__ raw,
    const float* __restrict__ fW1, const float* __restrict__ fb1)
{
    const int tid = threadIdx.x;
    __shared__ __align__(16) float sW1[64 * 76];   // fus_W1 padded 73 -> 76
    __shared__ float sb1[64];

    for (int i = tid; i < 64 * 76; i += 256) {
        int j = i / 76, k = i - j * 76;
        sW1[i] = (k < 73) ? fW1[j * 73 + k] : 0.0f;
    }
    if (tid < 64) sb1[tid] = fb1[tid];
    __syncthreads();

    const int idx = blockIdx.x * 256 + tid;
    const int b = idx >> 11;

    u64 zp[38];
    const float4* ep = (const float4*)(g_env1 + (size_t)idx * NHID);
#pragma unroll
    for (int i = 0; i < 16; ++i) {
        float4 v = ep[i];
        zp[2*i]   = pack2(v.x, v.y);
        zp[2*i+1] = pack2(v.z, v.w);
    }
    const int day = day_ids[b];
#pragma unroll
    for (int i = 0; i < 4; ++i)
        zp[32 + i] = pack2(g_traj[day * 8 + 2*i], g_traj[day * 8 + 2*i + 1]);

    float4 rv = ((const float4*)raw)[idx];
    float iphys = rv.x * 9.0f * (1.0f + 0.0005f * (rv.y - 0.5f));
    zp[36] = pack2(iphys, 0.f);
    zp[37] = 0;

    u64* f1out = (u64*)g_f1;
#pragma unroll 1
    for (int j = 0; j < 64; j += 2) {
        u64 a0x = pack2(sb1[j], 0.f),   a0y = 0;
        u64 a1x = pack2(sb1[j+1], 0.f), a1y = 0;
        const ulonglong2* w0 = (const ulonglong2*)(sW1 + (j+0) * 76);
        const ulonglong2* w1 = (const ulonglong2*)(sW1 + (j+1) * 76);
#pragma unroll
        for (int k2 = 0; k2 < 19; ++k2) {
            ulonglong2 x0 = w0[k2], x1 = w1[k2];
            if (k2 < 10) {
                fma2(a0x, x0.x, zp[2*k2]); fma2(a0x, x0.y, zp[2*k2+1]);
                fma2(a1x, x1.x, zp[2*k2]); fma2(a1x, x1.y, zp[2*k2+1]);
            } else {
                fma2(a0y, x0.x, zp[2*k2]); fma2(a0y, x0.y, zp[2*k2+1]);
                fma2(a1y, x1.x, zp[2*k2]); fma2(a1y, x1.y, zp[2*k2+1]);
            }
        }
        f1out[(size_t)(j >> 1) * NPOS + idx] =
            pack2(fmaxf(hsum2(a0x) + hsum2(a0y), 0.f),
                  fmaxf(hsum2(a1x) + hsum2(a1y), 0.f));
    }
}

// ============================================================================
// Fusion stage B: f1 -> f2 -> r1 -> outputs. 2 CTAs/SM; 4 chains in f2 dots.
// ============================================================================
__global__ __launch_bounds__(256, 2) void k_fusB(
    const int*   __restrict__ day_ids,
    const float* __restrict__ raw,
    const float* __restrict__ hdw, const float* __restrict__ hdb,
    const float* __restrict__ fW2, const float* __restrict__ fb2,
    const float* __restrict__ rW1, const float* __restrict__ rb1,
    const float* __restrict__ rW2, const float* __restrict__ rb2,
    float* __restrict__ out)
{
    const int tid = threadIdx.x;

    __shared__ __align__(16) float sW2[64 * 64];    // 16 kB (row-major)
    __shared__ __align__(16) u64   sR1t[64 * 16];   // 8 kB: [k][J]
    __shared__ __align__(16) float sR2[32];
    __shared__ float sb2[64], srb1[32];
    __shared__ float shdw[8];
    __shared__ float sscal[2];

    for (int i = tid; i < 64 * 64; i += 256) sW2[i] = fW2[i];
    for (int i = tid; i < 64 * 16; i += 256) {
        int k = i >> 4, J = i & 15;
        sR1t[i] = pack2(rW1[(2*J) * 64 + k], rW1[(2*J+1) * 64 + k]);
    }
    if (tid < 64) sb2[tid] = fb2[tid];
    if (tid < 32) { sR2[tid] = rW2[tid]; srb1[tid] = rb1[tid]; }
    if (tid < 8)  shdw[tid] = hdw[tid];
    if (tid == 0) { sscal[0] = hdb[0]; sscal[1] = rb2[0]; }
    __syncthreads();

    const int idx = blockIdx.x * 256 + tid;
    const int b = idx >> 11;

    u64 f1p[32];
    const u64* f1in = (const u64*)g_f1;
#pragma unroll
    for (int k2 = 0; k2 < 32; ++k2)
        f1p[k2] = f1in[(size_t)k2 * NPOS + idx];

    u64 r1acc[16];
#pragma unroll
    for (int J = 0; J < 16; ++J) r1acc[J] = pack2(srb1[2*J], srb1[2*J+1]);

#pragma unroll 1
    for (int jp = 0; jp < 32; ++jp) {
        u64 a0x = pack2(sb2[2*jp], 0.f),   a0y = 0;
        u64 a1x = pack2(sb2[2*jp+1], 0.f), a1y = 0;
        const ulonglong2* w0 = (const ulonglong2*)(sW2 + (2*jp+0) * 64);
        const ulonglong2* w1 = (const ulonglong2*)(sW2 + (2*jp+1) * 64);
#pragma unroll
        for (int k2 = 0; k2 < 16; ++k2) {
            ulonglong2 x0 = w0[k2], x1 = w1[k2];
            if (k2 < 8) {
                fma2(a0x, x0.x, f1p[2*k2]); fma2(a0x, x0.y, f1p[2*k2+1]);
                fma2(a1x, x1.x, f1p[2*k2]); fma2(a1x, x1.y, f1p[2*k2+1]);
            } else {
                fma2(a0y, x0.x, f1p[2*k2]); fma2(a0y, x0.y, f1p[2*k2+1]);
                fma2(a1y, x1.x, f1p[2*k2]); fma2(a1y, x1.y, f1p[2*k2+1]);
            }
        }
        float f2a = fmaxf(hsum2(a0x) + hsum2(a0y), 0.f);
        float f2b = fmaxf(hsum2(a1x) + hsum2(a1y), 0.f);
        u64 f2lo = pack2(f2a, f2a);
        u64 f2hi = pack2(f2b, f2b);
        const u64* wra = sR1t + (2*jp) * 16;
        const u64* wrb = sR1t + (2*jp+1) * 16;
#pragma unroll
        for (int J = 0; J < 16; ++J) {
            fma2(r1acc[J], wra[J], f2lo);
            fma2(r1acc[J], wrb[J], f2hi);
        }
    }

    u64 racc = pack2(sscal[1], 0.f);
    const u64* r2w = (const u64*)sR2;
#pragma unroll
    for (int J = 0; J < 16; ++J) {
        float lo, hi; unpack2(r1acc[J], lo, hi);
        fma2(racc, r2w[J], pack2(fmaxf(lo, 0.f), fmaxf(hi, 0.f)));
    }
    float r = hsum2(racc);

    const int day = day_ids[b];
    float health[8];
#pragma unroll
    for (int i = 0; i < 8; ++i) health[i] = g_traj[day * 8 + i];
    float4 rv = ((const float4*)raw)[idx];
    float iphys = rv.x * 9.0f * (1.0f + 0.0005f * (rv.y - 0.5f));
    float rawD = sscal[0];
#pragma unroll
    for (int i = 0; i < 8; ++i) rawD = fmaf(health[i], shdw[i], rawD);
    float D = fsig(rawD);

    float ibase = D * iphys;
    out[(size_t)0 * NPOS + idx] = ibase + r;   // I_pred
    out[(size_t)1 * NPOS + idx] = iphys;       // I_phys
    out[(size_t)2 * NPOS + idx] = ibase;       // I_base
    out[(size_t)3 * NPOS + idx] = D;           // D
    out[(size_t)4 * NPOS + idx] = r;           // r
    float* ho = out + (size_t)5 * NPOS + (size_t)idx * 8;
#pragma unroll
    for (int i = 0; i < 8; ++i) ho[i] = health[i];  // health_seq
}

// ---------------- launch ----------------------------------------------------
extern "C" void kernel_launch(void* const* d_in, const int* in_sizes, int n_in,
                              void* d_out, int out_size)
{
    const float* X        = (const float*)d_in[0];
    const int*   day_ids  = (const int*)  d_in[1];
    const float* raw      = (const float*)d_in[2];
    const float* ih0      = (const float*)d_in[3];
    const float* oW1      = (const float*)d_in[4];
    const float* ob1      = (const float*)d_in[5];
    const float* oW2      = (const float*)d_in[6];
    const float* ob2      = (const float*)d_in[7];
    const float* oW3      = (const float*)d_in[8];
    const float* ob3      = (const float*)d_in[9];
    const float* Wih0     = (const float*)d_in[10];
    const float* Whh0     = (const float*)d_in[11];
    const float* bih0     = (const float*)d_in[12];
    const float* bhh0     = (const float*)d_in[13];
    const float* Wih1     = (const float*)d_in[14];
    const float* Whh1     = (const float*)d_in[15];
    const float* bih1     = (const float*)d_in[16];
    const float* bhh1     = (const float*)d_in[17];
    const float* hdw      = (const float*)d_in[18];
    const float* hdb      = (const float*)d_in[19];
    const float* fW1      = (const float*)d_in[20];
    const float* fb1      = (const float*)d_in[21];
    const float* fW2      = (const float*)d_in[22];
    const float* fb2      = (const float*)d_in[23];
    const float* rW1      = (const float*)d_in[24];
    const float* rb1      = (const float*)d_in[25];
    const float* rW2      = (const float*)d_in[26];
    const float* rb2      = (const float*)d_in[27];

    float* gin0;  cudaGetSymbolAddress((void**)&gin0, g_gin0);

    // Stage Whh0 into the coalesced layout.
    k_stage<<<16, 256>>>(Whh0);
    // L0 input projection (parallel GEMM, f32x2, 4 CTAs/SM).
    k_gates0<<<NPOS / 128, 256>>>(X, Wih0, bih0, bhh0, gin0);
    // Fused L0+L1 recurrence (R8 structure + branch-free activations).
    k_recfused<<<129, 256>>>(Wih1, Whh1, bih1, bhh1,
                             ih0, oW1, ob1, oW2, ob2, oW3, ob3);
    // Fusion stage A: feat1 (2 CTAs/SM, 4 chains).
    k_fusA<<<NPOS / 256, 256>>>(day_ids, raw, fW1, fb1);
    // Fusion stage B: feat2 -> residual -> outputs (2 CTAs/SM, 4 chains).
    k_fusB<<<NPOS / 256, 256>>>(day_ids, raw, hdw, hdb,
                                fW2, fb2, rW1, rb1, rW2, rb2,
                                (float*)d_out);
}